// round 4
// baseline (speedup 1.0000x reference)
#include <cuda_runtime.h>
#include <math.h>

// ToneStack: 3 cascaded low-shelf biquads over x:[64, 480000] fp32.
// Blocked-recurrence decomposition:
//   pass_zero : per-chunk (128 samples) zero-state filtering -> final states
//   scan1/2/3 : hierarchical affine scan s_{k+1} = T s_k + f_k (T = A^128)
//   pass_final: per-chunk filtering from exact entry state, writes y.
// Warp owns 32 consecutive chunks; IO staged through a padded smem transpose
// in 32-sample tiles so every LDG/STG.128 covers 4 full 128B lines.

#define TLEN   480000
#define NROW   64
#define CHUNK  128
#define CROW   3750            // chunks per row
#define NCH    (NROW * CROW)   // 240000
#define NWARP  (NCH / 32)      // 7500
#define PBLK   (NWARP / 4)     // 1875 blocks of 4 warps
#define NGROUP 50
#define NGSZ   75              // NGROUP * NGSZ = CROW

__device__ float g_coef[15];          // per stage: b0, c1, c2, -a1, -a2
__device__ float g_T[36];             // A^CHUNK
__device__ float g_Tg[36];            // A^(CHUNK*NGSZ)
__device__ float g_states[NCH * 6];   // f_k, then overwritten with entry states
__device__ float g_grp[NROW * NGROUP * 6];
__device__ float g_entry[NROW * NGROUP * 6];

// ---------------------------------------------------------------- setup ----

__device__ void shelf_coefs(double fc, double gdb, double Q, double* out) {
    const double PI = 3.14159265358979323846;
    double A  = pow(10.0, gdb / 40.0);
    double w0 = 2.0 * PI * fc / 48000.0;
    double al = sin(w0) / (2.0 * Q);
    double cw = cos(w0);
    double sq = sqrt(A);
    double b0 = A * ((A + 1.0) - (A - 1.0) * cw + 2.0 * sq * al);
    double b1 = 2.0 * A * ((A - 1.0) - (A + 1.0) * cw);
    double b2 = A * ((A + 1.0) - (A - 1.0) * cw - 2.0 * sq * al);
    double a0 = (A + 1.0) + (A - 1.0) * cw + 2.0 * sq * al;
    double a1 = -2.0 * ((A - 1.0) + (A + 1.0) * cw);
    double a2 = (A + 1.0) + (A - 1.0) * cw - 2.0 * sq * al;
    b0 /= a0; b1 /= a0; b2 /= a0; a1 /= a0; a2 /= a0;
    out[0] = b0;
    out[1] = b1 - a1 * b0;   // c1
    out[2] = b2 - a2 * b0;   // c2
    out[3] = -a1;
    out[4] = -a2;
}

#define MATMUL(D, A_, B_)                                                     \
    do {                                                                      \
        if (tid < 36) {                                                       \
            int r_ = tid / 6, c_ = tid % 6;                                   \
            float acc_ = 0.f;                                                 \
            for (int k_ = 0; k_ < 6; k_++)                                    \
                acc_ += (A_)[r_ * 6 + k_] * (B_)[k_ * 6 + c_];                \
            (D)[tid] = acc_;                                                  \
        }                                                                     \
        __syncthreads();                                                      \
    } while (0)

__global__ void setup_kernel(const float* lg, const float* mg, const float* mfc,
                             const float* mq, const float* hg) {
    __shared__ double scoef[15];
    __shared__ float M0[36], M1[36], M2[36], M3[36], M4[36];
    int tid = threadIdx.x;

    if (tid == 0) {
        double c[5];
        shelf_coefs(120.0, (double)*lg, (double)0.707f, c);
        for (int i = 0; i < 5; i++) { scoef[i] = c[i];      g_coef[i]      = (float)c[i]; }
        shelf_coefs((double)*mfc, (double)*mg, (double)*mq, c);
        for (int i = 0; i < 5; i++) { scoef[5 + i] = c[i];  g_coef[5 + i]  = (float)c[i]; }
        shelf_coefs(4000.0, (double)*hg, (double)0.707f, c);
        for (int i = 0; i < 5; i++) { scoef[10 + i] = c[i]; g_coef[10 + i] = (float)c[i]; }
    }
    __syncthreads();

    // One-step 6x6 homogeneous matrix A: column j = step(e_j, x=0)
    if (tid < 6) {
        double z[6] = {0, 0, 0, 0, 0, 0};
        z[tid] = 1.0;
        double u = 0.0;
        double ns[6];
        for (int st = 0; st < 3; st++) {
            double b0  = scoef[st * 5 + 0], c1 = scoef[st * 5 + 1], c2 = scoef[st * 5 + 2];
            double na1 = scoef[st * 5 + 3], na2 = scoef[st * 5 + 4];
            double z1 = z[2 * st], z2 = z[2 * st + 1];
            double y = b0 * u + z1;
            ns[2 * st]     = c1 * u + na1 * z1 + z2;
            ns[2 * st + 1] = c2 * u + na2 * z1;
            u = y;
        }
        for (int i = 0; i < 6; i++) M0[i * 6 + tid] = (float)ns[i];
    }
    __syncthreads();

    // T = A^128 : 7 squarings (ends in M1)
    MATMUL(M1, M0, M0);   // A^2
    MATMUL(M0, M1, M1);   // A^4
    MATMUL(M1, M0, M0);   // A^8
    MATMUL(M0, M1, M1);   // A^16
    MATMUL(M1, M0, M0);   // A^32
    MATMUL(M0, M1, M1);   // A^64
    MATMUL(M1, M0, M0);   // A^128 = T
    if (tid < 36) { g_T[tid] = M1[tid]; M0[tid] = M1[tid]; }
    __syncthreads();

    // Tg = T^75 = T^64 * T^8 * T^2 * T
    MATMUL(M1, M0, M0);   // T^2
    MATMUL(M2, M1, M1);   // T^4
    MATMUL(M3, M2, M2);   // T^8
    MATMUL(M2, M3, M3);   // T^16
    MATMUL(M4, M2, M2);   // T^32
    MATMUL(M2, M4, M4);   // T^64
    MATMUL(M4, M2, M3);   // T^72
    MATMUL(M2, M4, M1);   // T^74
    MATMUL(M4, M2, M0);   // T^75
    if (tid < 36) g_Tg[tid] = M4[tid];
}

// -------------------------------------------------------------- filtering --

__device__ __forceinline__ float step_all(float u, float z[6], const float k[15]) {
    // stage 1
    float y0 = fmaf(k[0], u, z[0]);
    float t0 = fmaf(k[3], z[0], z[1]);
    z[1] = fmaf(k[2], u, k[4] * z[0]);
    z[0] = fmaf(k[1], u, t0);
    // stage 2
    float y1 = fmaf(k[5], y0, z[2]);
    float t1 = fmaf(k[8], z[2], z[3]);
    z[3] = fmaf(k[7], y0, k[9] * z[2]);
    z[2] = fmaf(k[6], y0, t1);
    // stage 3
    float y2 = fmaf(k[10], y1, z[4]);
    float t2 = fmaf(k[13], z[4], z[5]);
    z[5] = fmaf(k[12], y1, k[14] * z[4]);
    z[4] = fmaf(k[11], y1, t2);
    return y2;
}

// Tile: 32 chunks x 32 samples, rows padded to 36 floats.
// seg = lane>>3 (0..3), off = (lane&7)*4: each LDG/STG.128 covers 4 full lines.
// LDS/STS.128 per 8-lane phase hit banks 4*lane+c -> conflict-free.

__global__ __launch_bounds__(128) void pass_zero(const float* __restrict__ x) {
    __shared__ float sbuf[4][32][36];
    int wslot = threadIdx.x >> 5;
    int w = blockIdx.x * 4 + wslot;
    int lane = threadIdx.x & 31;
    float (*buf)[36] = sbuf[wslot];
    const float* xw = x + (size_t)w * (32 * CHUNK);

    float k[15];
#pragma unroll
    for (int i = 0; i < 15; i++) k[i] = g_coef[i];
    float z[6] = {0, 0, 0, 0, 0, 0};

    int seg = lane >> 3;
    int off = (lane & 7) * 4;

#pragma unroll
    for (int t = 0; t < CHUNK / 32; t++) {
        int toff = t * 32;
#pragma unroll
        for (int q = 0; q < 8; q++) {
            float4 v = *(const float4*)(xw + (q * 4 + seg) * CHUNK + toff + off);
            *(float4*)&buf[q * 4 + seg][off] = v;
        }
        __syncwarp();
        const float4* my = (const float4*)buf[lane];
#pragma unroll
        for (int j = 0; j < 8; j++) {
            float4 v = my[j];
            step_all(v.x, z, k);
            step_all(v.y, z, k);
            step_all(v.z, z, k);
            step_all(v.w, z, k);
        }
        __syncwarp();
    }
    float* f = &g_states[(size_t)(w * 32 + lane) * 6];
#pragma unroll
    for (int j = 0; j < 6; j++) f[j] = z[j];
}

__global__ __launch_bounds__(128) void pass_final(const float* __restrict__ x,
                                                  float* __restrict__ y) {
    __shared__ float sbuf[4][32][36];
    int wslot = threadIdx.x >> 5;
    int w = blockIdx.x * 4 + wslot;
    int lane = threadIdx.x & 31;
    float (*buf)[36] = sbuf[wslot];
    const float* xw = x + (size_t)w * (32 * CHUNK);
    float* yw = y + (size_t)w * (32 * CHUNK);

    float k[15];
#pragma unroll
    for (int i = 0; i < 15; i++) k[i] = g_coef[i];
    float z[6];
    const float* si = &g_states[(size_t)(w * 32 + lane) * 6];
#pragma unroll
    for (int j = 0; j < 6; j++) z[j] = si[j];

    int seg = lane >> 3;
    int off = (lane & 7) * 4;

#pragma unroll
    for (int t = 0; t < CHUNK / 32; t++) {
        int toff = t * 32;
#pragma unroll
        for (int q = 0; q < 8; q++) {
            float4 v = *(const float4*)(xw + (q * 4 + seg) * CHUNK + toff + off);
            *(float4*)&buf[q * 4 + seg][off] = v;
        }
        __syncwarp();
        float4* my = (float4*)buf[lane];
#pragma unroll
        for (int j = 0; j < 8; j++) {
            float4 v = my[j];
            float4 o;
            o.x = step_all(v.x, z, k);
            o.y = step_all(v.y, z, k);
            o.z = step_all(v.z, z, k);
            o.w = step_all(v.w, z, k);
            my[j] = o;
        }
        __syncwarp();
#pragma unroll
        for (int q = 0; q < 8; q++) {
            float4 v = *(const float4*)&buf[q * 4 + seg][off];
            *(float4*)(yw + (q * 4 + seg) * CHUNK + toff + off) = v;
        }
        __syncwarp();
    }
}

// ------------------------------------------------------------------ scans --

// scan1: one warp per (row, group): stage 75 chunk-finals to smem, lane 0
// scans with T from zero state -> group final.
__global__ __launch_bounds__(32) void scan1() {
    __shared__ float sf[NGSZ * 6];
    int b = blockIdx.x;
    int lane = threadIdx.x;
    const float* fp = &g_states[(size_t)b * NGSZ * 6];
    for (int i = lane; i < NGSZ * 6 / 2; i += 32)
        ((float2*)sf)[i] = ((const float2*)fp)[i];
    __syncwarp();
    if (lane == 0) {
        float T[36];
#pragma unroll
        for (int i = 0; i < 36; i++) T[i] = g_T[i];
        float s[6] = {0, 0, 0, 0, 0, 0};
        for (int i = 0; i < NGSZ; i++) {
            float ns[6];
#pragma unroll
            for (int j = 0; j < 6; j++) {
                float acc = sf[i * 6 + j];
#pragma unroll
                for (int kk = 0; kk < 6; kk++) acc = fmaf(T[j * 6 + kk], s[kk], acc);
                ns[j] = acc;
            }
#pragma unroll
            for (int j = 0; j < 6; j++) s[j] = ns[j];
        }
        float* o = &g_grp[(size_t)b * 6];
#pragma unroll
        for (int j = 0; j < 6; j++) o[j] = s[j];
    }
}

// scan2: one warp per row: serial scan over 50 group finals with Tg,
// emitting each group's entry state.
__global__ __launch_bounds__(32) void scan2() {
    __shared__ float sf[NGROUP * 6];
    __shared__ float se[NGROUP * 6];
    int r = blockIdx.x;
    int lane = threadIdx.x;
    const float* gp = &g_grp[(size_t)r * NGROUP * 6];
    for (int i = lane; i < NGROUP * 6 / 2; i += 32)
        ((float2*)sf)[i] = ((const float2*)gp)[i];
    __syncwarp();
    if (lane == 0) {
        float T[36];
#pragma unroll
        for (int i = 0; i < 36; i++) T[i] = g_Tg[i];
        float s[6] = {0, 0, 0, 0, 0, 0};
        for (int g = 0; g < NGROUP; g++) {
#pragma unroll
            for (int j = 0; j < 6; j++) se[g * 6 + j] = s[j];
            float ns[6];
#pragma unroll
            for (int j = 0; j < 6; j++) {
                float acc = sf[g * 6 + j];
#pragma unroll
                for (int kk = 0; kk < 6; kk++) acc = fmaf(T[j * 6 + kk], s[kk], acc);
                ns[j] = acc;
            }
#pragma unroll
            for (int j = 0; j < 6; j++) s[j] = ns[j];
        }
    }
    __syncwarp();
    float* ep = &g_entry[(size_t)r * NGROUP * 6];
    for (int i = lane; i < NGROUP * 6 / 2; i += 32)
        ((float2*)ep)[i] = ((const float2*)se)[i];
}

// scan3: one warp per (row, group): stage finals, scan from true entry,
// overwrite g_states with per-chunk entry states.
__global__ __launch_bounds__(32) void scan3() {
    __shared__ float sf[NGSZ * 6];
    int b = blockIdx.x;
    int lane = threadIdx.x;
    float* fp = &g_states[(size_t)b * NGSZ * 6];
    for (int i = lane; i < NGSZ * 6 / 2; i += 32)
        ((float2*)sf)[i] = ((const float2*)fp)[i];
    __syncwarp();
    if (lane == 0) {
        float T[36];
#pragma unroll
        for (int i = 0; i < 36; i++) T[i] = g_T[i];
        float s[6];
        const float* e = &g_entry[(size_t)b * 6];
#pragma unroll
        for (int j = 0; j < 6; j++) s[j] = e[j];
        for (int i = 0; i < NGSZ; i++) {
            float fv[6];
#pragma unroll
            for (int j = 0; j < 6; j++) { fv[j] = sf[i * 6 + j]; sf[i * 6 + j] = s[j]; }
            float ns[6];
#pragma unroll
            for (int j = 0; j < 6; j++) {
                float acc = fv[j];
#pragma unroll
                for (int kk = 0; kk < 6; kk++) acc = fmaf(T[j * 6 + kk], s[kk], acc);
                ns[j] = acc;
            }
#pragma unroll
            for (int j = 0; j < 6; j++) s[j] = ns[j];
        }
    }
    __syncwarp();
    for (int i = lane; i < NGSZ * 6 / 2; i += 32)
        ((float2*)fp)[i] = ((const float2*)sf)[i];
}

// ----------------------------------------------------------------- launch --

extern "C" void kernel_launch(void* const* d_in, const int* in_sizes, int n_in,
                              void* d_out, int out_size) {
    const float* x   = (const float*)d_in[0];
    const float* lg  = (const float*)d_in[1];
    const float* mg  = (const float*)d_in[2];
    const float* mfc = (const float*)d_in[3];
    const float* mq  = (const float*)d_in[4];
    const float* hg  = (const float*)d_in[5];
    float* y = (float*)d_out;

    setup_kernel<<<1, 256>>>(lg, mg, mfc, mq, hg);

    pass_zero<<<PBLK, 128>>>(x);
    scan1<<<NROW * NGROUP, 32>>>();
    scan2<<<NROW, 32>>>();
    scan3<<<NROW * NGROUP, 32>>>();
    pass_final<<<PBLK, 128>>>(x, y);
}

// round 5
// speedup vs baseline: 1.0639x; 1.0639x over previous
#include <cuda_runtime.h>
#include <math.h>

// ToneStack: 3 cascaded low-shelf biquads over x:[64, 480000] fp32.
// Blocked-recurrence decomposition:
//   pass_zero : per-chunk (128 samples) zero-state filtering -> final states
//   scan_fused: per-row 3-level affine scan s_{k+1} = T s_k + f_k (one kernel)
//   pass_final: per-chunk filtering from exact entry state, writes y.
// Warp owns 32 consecutive chunks; IO staged through a padded smem transpose
// in 32-sample tiles (4 full 128B lines per LDG/STG.128), with next-tile
// prefetch overlapping compute.

#define TLEN   480000
#define NROW   64
#define CHUNK  128
#define CROW   3750            // chunks per row
#define NCH    (NROW * CROW)   // 240000
#define NWARP  (NCH / 32)      // 7500
#define PBLK   (NWARP / 4)     // 1875 blocks of 4 warps
#define NGSZ   30              // chunks per group
#define NGROUP 125             // groups per row
#define NSUPG  5               // groups per supergroup
#define NSUP   25              // supergroups per row

__device__ float g_coef[15];          // per stage: b0, c1, c2, -a1, -a2
__device__ float g_T[36];             // A^CHUNK
__device__ float g_Tg[36];            // T^NGSZ
__device__ float g_Tsg[36];           // Tg^NSUPG
__device__ float g_states[NCH * 6];   // finals, then overwritten with entries

// ---------------------------------------------------------------- setup ----

__device__ void shelf_coefs(double fc, double gdb, double Q, double* out) {
    const double PI = 3.14159265358979323846;
    double A  = pow(10.0, gdb / 40.0);
    double w0 = 2.0 * PI * fc / 48000.0;
    double al = sin(w0) / (2.0 * Q);
    double cw = cos(w0);
    double sq = sqrt(A);
    double b0 = A * ((A + 1.0) - (A - 1.0) * cw + 2.0 * sq * al);
    double b1 = 2.0 * A * ((A - 1.0) - (A + 1.0) * cw);
    double b2 = A * ((A + 1.0) - (A - 1.0) * cw - 2.0 * sq * al);
    double a0 = (A + 1.0) + (A - 1.0) * cw + 2.0 * sq * al;
    double a1 = -2.0 * ((A - 1.0) + (A + 1.0) * cw);
    double a2 = (A + 1.0) + (A - 1.0) * cw - 2.0 * sq * al;
    b0 /= a0; b1 /= a0; b2 /= a0; a1 /= a0; a2 /= a0;
    out[0] = b0;
    out[1] = b1 - a1 * b0;   // c1
    out[2] = b2 - a2 * b0;   // c2
    out[3] = -a1;
    out[4] = -a2;
}

#define MATMUL(D, A_, B_)                                                     \
    do {                                                                      \
        if (tid < 36) {                                                       \
            int r_ = tid / 6, c_ = tid % 6;                                   \
            float acc_ = 0.f;                                                 \
            for (int k_ = 0; k_ < 6; k_++)                                    \
                acc_ += (A_)[r_ * 6 + k_] * (B_)[k_ * 6 + c_];                \
            (D)[tid] = acc_;                                                  \
        }                                                                     \
        __syncthreads();                                                      \
    } while (0)

__global__ void setup_kernel(const float* lg, const float* mg, const float* mfc,
                             const float* mq, const float* hg) {
    __shared__ double scoef[15];
    __shared__ float M0[36], M1[36], M2[36], M3[36], M4[36];
    int tid = threadIdx.x;

    if (tid == 0) {
        double c[5];
        shelf_coefs(120.0, (double)*lg, (double)0.707f, c);
        for (int i = 0; i < 5; i++) { scoef[i] = c[i];      g_coef[i]      = (float)c[i]; }
        shelf_coefs((double)*mfc, (double)*mg, (double)*mq, c);
        for (int i = 0; i < 5; i++) { scoef[5 + i] = c[i];  g_coef[5 + i]  = (float)c[i]; }
        shelf_coefs(4000.0, (double)*hg, (double)0.707f, c);
        for (int i = 0; i < 5; i++) { scoef[10 + i] = c[i]; g_coef[10 + i] = (float)c[i]; }
    }
    __syncthreads();

    // One-step 6x6 homogeneous matrix A: column j = step(e_j, x=0)
    if (tid < 6) {
        double z[6] = {0, 0, 0, 0, 0, 0};
        z[tid] = 1.0;
        double u = 0.0;
        double ns[6];
        for (int st = 0; st < 3; st++) {
            double b0  = scoef[st * 5 + 0], c1 = scoef[st * 5 + 1], c2 = scoef[st * 5 + 2];
            double na1 = scoef[st * 5 + 3], na2 = scoef[st * 5 + 4];
            double z1 = z[2 * st], z2 = z[2 * st + 1];
            double y = b0 * u + z1;
            ns[2 * st]     = c1 * u + na1 * z1 + z2;
            ns[2 * st + 1] = c2 * u + na2 * z1;
            u = y;
        }
        for (int i = 0; i < 6; i++) M0[i * 6 + tid] = (float)ns[i];
    }
    __syncthreads();

    // T = A^128 : 7 squarings
    MATMUL(M1, M0, M0);   // A^2
    MATMUL(M0, M1, M1);   // A^4
    MATMUL(M1, M0, M0);   // A^8
    MATMUL(M0, M1, M1);   // A^16
    MATMUL(M1, M0, M0);   // A^32
    MATMUL(M0, M1, M1);   // A^64
    MATMUL(M1, M0, M0);   // A^128 = T
    if (tid < 36) { g_T[tid] = M1[tid]; M0[tid] = M1[tid]; }
    __syncthreads();

    // Tg = T^30 = T^16 * T^8 * T^4 * T^2 ; Tsg = Tg^5
    MATMUL(M1, M0, M0);   // T^2
    MATMUL(M2, M1, M1);   // T^4
    MATMUL(M3, M2, M2);   // T^8
    MATMUL(M4, M3, M3);   // T^16
    MATMUL(M0, M4, M3);   // T^24
    MATMUL(M3, M0, M2);   // T^28
    MATMUL(M2, M3, M1);   // T^30 = Tg
    if (tid < 36) g_Tg[tid] = M2[tid];
    __syncthreads();
    MATMUL(M1, M2, M2);   // Tg^2
    MATMUL(M0, M1, M1);   // Tg^4
    MATMUL(M4, M0, M2);   // Tg^5 = Tsg
    if (tid < 36) g_Tsg[tid] = M4[tid];
}

// -------------------------------------------------------------- filtering --

__device__ __forceinline__ float step_all(float u, float z[6], const float k[15]) {
    // stage 1
    float y0 = fmaf(k[0], u, z[0]);
    float t0 = fmaf(k[3], z[0], z[1]);
    z[1] = fmaf(k[2], u, k[4] * z[0]);
    z[0] = fmaf(k[1], u, t0);
    // stage 2
    float y1 = fmaf(k[5], y0, z[2]);
    float t1 = fmaf(k[8], z[2], z[3]);
    z[3] = fmaf(k[7], y0, k[9] * z[2]);
    z[2] = fmaf(k[6], y0, t1);
    // stage 3
    float y2 = fmaf(k[10], y1, z[4]);
    float t2 = fmaf(k[13], z[4], z[5]);
    z[5] = fmaf(k[12], y1, k[14] * z[4]);
    z[4] = fmaf(k[11], y1, t2);
    return y2;
}

// Tile: 32 chunks x 32 samples, rows padded to 36 floats.
// seg = lane>>3 (0..3), off = (lane&7)*4: every LDG/STG.128 covers 4 full
// 128B lines; LDS/STS.128 are phase-conflict-free.

__global__ __launch_bounds__(128) void pass_zero(const float* __restrict__ x) {
    __shared__ float sbuf[4][32][36];
    int wslot = threadIdx.x >> 5;
    int w = blockIdx.x * 4 + wslot;
    int lane = threadIdx.x & 31;
    float (*buf)[36] = sbuf[wslot];
    const float* xw = x + (size_t)w * (32 * CHUNK);

    float k[15];
#pragma unroll
    for (int i = 0; i < 15; i++) k[i] = g_coef[i];
    float z[6] = {0, 0, 0, 0, 0, 0};

    int seg = lane >> 3;
    int off = (lane & 7) * 4;

    float4 pre[8];
#pragma unroll
    for (int q = 0; q < 8; q++)
        pre[q] = *(const float4*)(xw + (q * 4 + seg) * CHUNK + off);

#pragma unroll
    for (int t = 0; t < CHUNK / 32; t++) {
#pragma unroll
        for (int q = 0; q < 8; q++)
            *(float4*)&buf[q * 4 + seg][off] = pre[q];
        __syncwarp();
        if (t < CHUNK / 32 - 1) {
#pragma unroll
            for (int q = 0; q < 8; q++)
                pre[q] = *(const float4*)(xw + (q * 4 + seg) * CHUNK + (t + 1) * 32 + off);
        }
        const float4* my = (const float4*)buf[lane];
#pragma unroll
        for (int j = 0; j < 8; j++) {
            float4 v = my[j];
            step_all(v.x, z, k);
            step_all(v.y, z, k);
            step_all(v.z, z, k);
            step_all(v.w, z, k);
        }
        __syncwarp();
    }
    float* f = &g_states[(size_t)(w * 32 + lane) * 6];
#pragma unroll
    for (int j = 0; j < 6; j++) f[j] = z[j];
}

__global__ __launch_bounds__(128) void pass_final(const float* __restrict__ x,
                                                  float* __restrict__ y) {
    __shared__ float sbuf[4][32][36];
    int wslot = threadIdx.x >> 5;
    int w = blockIdx.x * 4 + wslot;
    int lane = threadIdx.x & 31;
    float (*buf)[36] = sbuf[wslot];
    const float* xw = x + (size_t)w * (32 * CHUNK);
    float* yw = y + (size_t)w * (32 * CHUNK);

    float k[15];
#pragma unroll
    for (int i = 0; i < 15; i++) k[i] = g_coef[i];
    float z[6];
    const float* si = &g_states[(size_t)(w * 32 + lane) * 6];
#pragma unroll
    for (int j = 0; j < 6; j++) z[j] = si[j];

    int seg = lane >> 3;
    int off = (lane & 7) * 4;

    float4 pre[8];
#pragma unroll
    for (int q = 0; q < 8; q++)
        pre[q] = *(const float4*)(xw + (q * 4 + seg) * CHUNK + off);

#pragma unroll
    for (int t = 0; t < CHUNK / 32; t++) {
#pragma unroll
        for (int q = 0; q < 8; q++)
            *(float4*)&buf[q * 4 + seg][off] = pre[q];
        __syncwarp();
        if (t < CHUNK / 32 - 1) {
#pragma unroll
            for (int q = 0; q < 8; q++)
                pre[q] = *(const float4*)(xw + (q * 4 + seg) * CHUNK + (t + 1) * 32 + off);
        }
        float4* my = (float4*)buf[lane];
#pragma unroll
        for (int j = 0; j < 8; j++) {
            float4 v = my[j];
            float4 o;
            o.x = step_all(v.x, z, k);
            o.y = step_all(v.y, z, k);
            o.z = step_all(v.z, z, k);
            o.w = step_all(v.w, z, k);
            my[j] = o;
        }
        __syncwarp();
#pragma unroll
        for (int q = 0; q < 8; q++) {
            float4 v = *(const float4*)&buf[q * 4 + seg][off];
            *(float4*)(yw + (q * 4 + seg) * CHUNK + t * 32 + off) = v;
        }
        __syncwarp();
    }
}

// ------------------------------------------------------------ fused scan --

__device__ __forceinline__ void affine_step(float s[6], const float fv[6],
                                            const float T[36]) {
    float ns[6];
#pragma unroll
    for (int j = 0; j < 6; j++) {
        float acc = fv[j];
#pragma unroll
        for (int kk = 0; kk < 6; kk++) acc = fmaf(T[j * 6 + kk], s[kk], acc);
        ns[j] = acc;
    }
#pragma unroll
    for (int j = 0; j < 6; j++) s[j] = ns[j];
}

// One block per row; 3-level scan (125 groups of 30, 25 supergroups of 5).
// Finals streamed from L2; entries written back over g_states.
__global__ __launch_bounds__(128) void scan_fused() {
    __shared__ float sT[36], sTg[36], sTsg[36];
    __shared__ float grp[NGROUP][6];
    __shared__ float sup[NSUP][6];
    int r = blockIdx.x, tid = threadIdx.x;
    float* gs = &g_states[(size_t)r * CROW * 6];

    if (tid < 36) { sT[tid] = g_T[tid]; sTg[tid] = g_Tg[tid]; sTsg[tid] = g_Tsg[tid]; }
    __syncthreads();

    // phase 1: zero-entry scan within each group -> group final
    if (tid < NGROUP) {
        float T[36];
#pragma unroll
        for (int i = 0; i < 36; i++) T[i] = sT[i];
        const float* f = &gs[(size_t)tid * NGSZ * 6];
        float s[6] = {0, 0, 0, 0, 0, 0};
        float fv[6], nx[6];
#pragma unroll
        for (int j = 0; j < 6; j++) fv[j] = f[j];
        for (int i = 0; i < NGSZ; i++) {
            if (i < NGSZ - 1) {
#pragma unroll
                for (int j = 0; j < 6; j++) nx[j] = f[(i + 1) * 6 + j];
            }
            affine_step(s, fv, T);
#pragma unroll
            for (int j = 0; j < 6; j++) fv[j] = nx[j];
        }
#pragma unroll
        for (int j = 0; j < 6; j++) grp[tid][j] = s[j];
    }
    __syncthreads();

    // phase 2a: zero-entry scan of 5 group finals -> supergroup final
    if (tid < NSUP) {
        float T[36];
#pragma unroll
        for (int i = 0; i < 36; i++) T[i] = sTg[i];
        float s[6] = {0, 0, 0, 0, 0, 0};
        for (int i = 0; i < NSUPG; i++) affine_step(s, grp[tid * NSUPG + i], T);
#pragma unroll
        for (int j = 0; j < 6; j++) sup[tid][j] = s[j];
    }
    __syncthreads();

    // phase 2b: serial scan over 25 supergroups; sup[] becomes entry states
    if (tid == 0) {
        float T[36];
#pragma unroll
        for (int i = 0; i < 36; i++) T[i] = sTsg[i];
        float s[6] = {0, 0, 0, 0, 0, 0};
        for (int g = 0; g < NSUP; g++) {
            float fv[6];
#pragma unroll
            for (int j = 0; j < 6; j++) { fv[j] = sup[g][j]; sup[g][j] = s[j]; }
            affine_step(s, fv, T);
        }
    }
    __syncthreads();

    // phase 2c: group entry states from supergroup entry
    if (tid < NSUP) {
        float T[36];
#pragma unroll
        for (int i = 0; i < 36; i++) T[i] = sTg[i];
        float s[6];
#pragma unroll
        for (int j = 0; j < 6; j++) s[j] = sup[tid][j];
        for (int i = 0; i < NSUPG; i++) {
            float fv[6];
            int gi = tid * NSUPG + i;
#pragma unroll
            for (int j = 0; j < 6; j++) { fv[j] = grp[gi][j]; grp[gi][j] = s[j]; }
            affine_step(s, fv, T);
        }
    }
    __syncthreads();

    // phase 3: per-chunk entry states, overwrite g_states
    if (tid < NGROUP) {
        float T[36];
#pragma unroll
        for (int i = 0; i < 36; i++) T[i] = sT[i];
        float* f = &gs[(size_t)tid * NGSZ * 6];
        float s[6];
#pragma unroll
        for (int j = 0; j < 6; j++) s[j] = grp[tid][j];
        float fv[6], nx[6];
#pragma unroll
        for (int j = 0; j < 6; j++) fv[j] = f[j];
        for (int i = 0; i < NGSZ; i++) {
            if (i < NGSZ - 1) {
#pragma unroll
                for (int j = 0; j < 6; j++) nx[j] = f[(i + 1) * 6 + j];
            }
#pragma unroll
            for (int j = 0; j < 6; j++) f[i * 6 + j] = s[j];
            affine_step(s, fv, T);
#pragma unroll
            for (int j = 0; j < 6; j++) fv[j] = nx[j];
        }
    }
}

// ----------------------------------------------------------------- launch --

extern "C" void kernel_launch(void* const* d_in, const int* in_sizes, int n_in,
                              void* d_out, int out_size) {
    const float* x   = (const float*)d_in[0];
    const float* lg  = (const float*)d_in[1];
    const float* mg  = (const float*)d_in[2];
    const float* mfc = (const float*)d_in[3];
    const float* mq  = (const float*)d_in[4];
    const float* hg  = (const float*)d_in[5];
    float* y = (float*)d_out;

    setup_kernel<<<1, 256>>>(lg, mg, mfc, mq, hg);

    pass_zero<<<PBLK, 128>>>(x);
    scan_fused<<<NROW, 128>>>();
    pass_final<<<PBLK, 128>>>(x, y);
}

// round 6
// speedup vs baseline: 1.1017x; 1.0355x over previous
#include <cuda_runtime.h>
#include <math.h>

// ToneStack: 3 cascaded low-shelf biquads over x:[64, 480000] fp32.
// Blocked-recurrence decomposition:
//   pass_zero : per-chunk zero-state FINAL via weighted reduction
//               f = sum_n W[n]*x[n]  (W[n] = A^(127-n) b, shared by all chunks)
//   scan_fused: per-row 3-level affine scan s_{k+1} = T s_k + f_k,
//               staged through padded smem (coalesced, conflict-free)
//   pass_final: per-chunk serial filtering from exact entry state, writes y.

#define TLEN   480000
#define NROW   64
#define CHUNK  128
#define CROW   3750            // chunks per row
#define NCH    (NROW * CROW)   // 240000
#define NWARP  (NCH / 32)      // 7500
#define PBLK   (NWARP / 4)     // 1875 blocks of 4 warps
#define NGSZ   30              // chunks per group
#define NGROUP 125             // groups per row
#define NSUPG  5               // groups per supergroup
#define NSUP   25              // supergroups per row
#define GPAD   181             // NGSZ*6 + 1 (odd -> conflict-free smem rows)
#define SCAN_SMEM (NGROUP * GPAD * 4)

__device__ float g_coef[15];          // per stage: b0, c1, c2, -a1, -a2
__device__ float g_T[36];             // A^CHUNK
__device__ float g_Tg[36];            // T^NGSZ
__device__ float g_Tsg[36];           // Tg^NSUPG
__device__ float g_W[CHUNK][8];       // reduction weights (cols 6,7 = 0)
__device__ float g_states[NCH * 6];   // finals, then overwritten with entries

// ---------------------------------------------------------------- setup ----

__device__ void shelf_coefs(double fc, double gdb, double Q, double* out) {
    const double PI = 3.14159265358979323846;
    double A  = pow(10.0, gdb / 40.0);
    double w0 = 2.0 * PI * fc / 48000.0;
    double al = sin(w0) / (2.0 * Q);
    double cw = cos(w0);
    double sq = sqrt(A);
    double b0 = A * ((A + 1.0) - (A - 1.0) * cw + 2.0 * sq * al);
    double b1 = 2.0 * A * ((A - 1.0) - (A + 1.0) * cw);
    double b2 = A * ((A + 1.0) - (A - 1.0) * cw - 2.0 * sq * al);
    double a0 = (A + 1.0) + (A - 1.0) * cw + 2.0 * sq * al;
    double a1 = -2.0 * ((A - 1.0) + (A + 1.0) * cw);
    double a2 = (A + 1.0) + (A - 1.0) * cw - 2.0 * sq * al;
    b0 /= a0; b1 /= a0; b2 /= a0; a1 /= a0; a2 /= a0;
    out[0] = b0;
    out[1] = b1 - a1 * b0;   // c1
    out[2] = b2 - a2 * b0;   // c2
    out[3] = -a1;
    out[4] = -a2;
}

#define MATMUL(D, A_, B_)                                                     \
    do {                                                                      \
        if (tid < 36) {                                                       \
            int r_ = tid / 6, c_ = tid % 6;                                   \
            float acc_ = 0.f;                                                 \
            for (int k_ = 0; k_ < 6; k_++)                                    \
                acc_ += (A_)[r_ * 6 + k_] * (B_)[k_ * 6 + c_];                \
            (D)[tid] = acc_;                                                  \
        }                                                                     \
        __syncthreads();                                                      \
    } while (0)

__global__ void setup_kernel(const float* lg, const float* mg, const float* mfc,
                             const float* mq, const float* hg) {
    __shared__ double scoef[15];
    __shared__ double dA[36], db[6];
    __shared__ float M0[36], M1[36], M2[36], M3[36], M4[36];
    int tid = threadIdx.x;

    if (tid == 0) {
        double c[5];
        shelf_coefs(120.0, (double)*lg, (double)0.707f, c);
        for (int i = 0; i < 5; i++) { scoef[i] = c[i];      g_coef[i]      = (float)c[i]; }
        shelf_coefs((double)*mfc, (double)*mg, (double)*mq, c);
        for (int i = 0; i < 5; i++) { scoef[5 + i] = c[i];  g_coef[5 + i]  = (float)c[i]; }
        shelf_coefs(4000.0, (double)*hg, (double)0.707f, c);
        for (int i = 0; i < 5; i++) { scoef[10 + i] = c[i]; g_coef[10 + i] = (float)c[i]; }
    }
    __syncthreads();

    // One-step 6x6 homogeneous matrix A: column j = step(e_j, x=0)
    if (tid < 6) {
        double z[6] = {0, 0, 0, 0, 0, 0};
        z[tid] = 1.0;
        double u = 0.0;
        double ns[6];
        for (int st = 0; st < 3; st++) {
            double b0  = scoef[st * 5 + 0], c1 = scoef[st * 5 + 1], c2 = scoef[st * 5 + 2];
            double na1 = scoef[st * 5 + 3], na2 = scoef[st * 5 + 4];
            double z1 = z[2 * st], z2 = z[2 * st + 1];
            double y = b0 * u + z1;
            ns[2 * st]     = c1 * u + na1 * z1 + z2;
            ns[2 * st + 1] = c2 * u + na2 * z1;
            u = y;
        }
        for (int i = 0; i < 6; i++) { M0[i * 6 + tid] = (float)ns[i]; dA[i * 6 + tid] = ns[i]; }
    }
    // Input vector b: state update from z=0, u=1
    if (tid == 0) {
        double y0 = scoef[0];                 // b0_1
        double y1 = scoef[5] * y0;            // b0_2 * y0
        db[0] = scoef[1];  db[1] = scoef[2];
        db[2] = scoef[6] * y0;   db[3] = scoef[7] * y0;
        db[4] = scoef[11] * y1;  db[5] = scoef[12] * y1;
    }
    __syncthreads();

    // T = A^128 : 7 squarings
    MATMUL(M1, M0, M0);   // A^2
    MATMUL(M0, M1, M1);   // A^4
    MATMUL(M1, M0, M0);   // A^8
    MATMUL(M0, M1, M1);   // A^16
    MATMUL(M1, M0, M0);   // A^32
    MATMUL(M0, M1, M1);   // A^64
    MATMUL(M1, M0, M0);   // A^128 = T
    if (tid < 36) { g_T[tid] = M1[tid]; M0[tid] = M1[tid]; }
    __syncthreads();

    // Tg = T^30 ; Tsg = Tg^5
    MATMUL(M1, M0, M0);   // T^2
    MATMUL(M2, M1, M1);   // T^4
    MATMUL(M3, M2, M2);   // T^8
    MATMUL(M4, M3, M3);   // T^16
    MATMUL(M0, M4, M3);   // T^24
    MATMUL(M3, M0, M2);   // T^28
    MATMUL(M2, M3, M1);   // T^30 = Tg
    if (tid < 36) g_Tg[tid] = M2[tid];
    __syncthreads();
    MATMUL(M1, M2, M2);   // Tg^2
    MATMUL(M0, M1, M1);   // Tg^4
    MATMUL(M4, M0, M2);   // Tg^5 = Tsg
    if (tid < 36) g_Tsg[tid] = M4[tid];

    // Reduction weights: W[n] = A^(127-n) b   (fp32 iteration, 128 matvecs)
    if (tid == 0) {
        float fA[36];
        for (int i = 0; i < 36; i++) fA[i] = (float)dA[i];
        float v[6];
        for (int j = 0; j < 6; j++) v[j] = (float)db[j];
        for (int n = CHUNK - 1; n >= 0; n--) {
            for (int j = 0; j < 6; j++) g_W[n][j] = v[j];
            g_W[n][6] = 0.f; g_W[n][7] = 0.f;
            float nv[6];
            for (int j = 0; j < 6; j++) {
                float acc = 0.f;
                for (int kk = 0; kk < 6; kk++) acc = fmaf(fA[j * 6 + kk], v[kk], acc);
                nv[j] = acc;
            }
            for (int j = 0; j < 6; j++) v[j] = nv[j];
        }
    }
}

// -------------------------------------------------------------- filtering --

__device__ __forceinline__ float step_all(float u, float z[6], const float k[15]) {
    float y0 = fmaf(k[0], u, z[0]);
    float t0 = fmaf(k[3], z[0], z[1]);
    z[1] = fmaf(k[2], u, k[4] * z[0]);
    z[0] = fmaf(k[1], u, t0);
    float y1 = fmaf(k[5], y0, z[2]);
    float t1 = fmaf(k[8], z[2], z[3]);
    z[3] = fmaf(k[7], y0, k[9] * z[2]);
    z[2] = fmaf(k[6], y0, t1);
    float y2 = fmaf(k[10], y1, z[4]);
    float t2 = fmaf(k[13], z[4], z[5]);
    z[5] = fmaf(k[12], y1, k[14] * z[4]);
    z[4] = fmaf(k[11], y1, t2);
    return y2;
}

// Tile: 32 chunks x 32 samples, rows padded to 36 floats. seg = lane>>3,
// off = (lane&7)*4: every LDG/STG.128 covers 4 full 128B lines.

// pass_zero: weighted reduction f = sum_n W[n] * x[n]. 6 independent
// accumulators per thread; weights broadcast from smem.
__global__ __launch_bounds__(128) void pass_zero(const float* __restrict__ x) {
    __shared__ float sbuf[4][32][36];
    __shared__ float sw[CHUNK][8];
    int wslot = threadIdx.x >> 5;
    int w = blockIdx.x * 4 + wslot;
    int lane = threadIdx.x & 31;
    float (*buf)[36] = sbuf[wslot];
    const float* xw = x + (size_t)w * (32 * CHUNK);

    for (int i = threadIdx.x; i < CHUNK * 2; i += 128)
        ((float4*)sw)[i] = ((const float4*)g_W)[i];
    __syncthreads();

    float f0 = 0.f, f1 = 0.f, f2 = 0.f, f3 = 0.f, f4 = 0.f, f5 = 0.f;
    int seg = lane >> 3;
    int off = (lane & 7) * 4;

    float4 pre[8];
#pragma unroll
    for (int q = 0; q < 8; q++)
        pre[q] = *(const float4*)(xw + (q * 4 + seg) * CHUNK + off);

#pragma unroll
    for (int t = 0; t < CHUNK / 32; t++) {
#pragma unroll
        for (int q = 0; q < 8; q++)
            *(float4*)&buf[q * 4 + seg][off] = pre[q];
        __syncwarp();
        if (t < CHUNK / 32 - 1) {
#pragma unroll
            for (int q = 0; q < 8; q++)
                pre[q] = *(const float4*)(xw + (q * 4 + seg) * CHUNK + (t + 1) * 32 + off);
        }
        const float4* my = (const float4*)buf[lane];
#pragma unroll
        for (int j = 0; j < 8; j++) {
            float4 v = my[j];
            int n = t * 32 + j * 4;
#pragma unroll
            for (int e = 0; e < 4; e++) {
                float u = (e == 0) ? v.x : (e == 1) ? v.y : (e == 2) ? v.z : v.w;
                const float* wn = sw[n + e];
                f0 = fmaf(u, wn[0], f0);
                f1 = fmaf(u, wn[1], f1);
                f2 = fmaf(u, wn[2], f2);
                f3 = fmaf(u, wn[3], f3);
                f4 = fmaf(u, wn[4], f4);
                f5 = fmaf(u, wn[5], f5);
            }
        }
        __syncwarp();
    }
    float* f = &g_states[(size_t)(w * 32 + lane) * 6];
    f[0] = f0; f[1] = f1; f[2] = f2; f[3] = f3; f[4] = f4; f[5] = f5;
}

__global__ __launch_bounds__(128) void pass_final(const float* __restrict__ x,
                                                  float* __restrict__ y) {
    __shared__ float sbuf[4][32][36];
    int wslot = threadIdx.x >> 5;
    int w = blockIdx.x * 4 + wslot;
    int lane = threadIdx.x & 31;
    float (*buf)[36] = sbuf[wslot];
    const float* xw = x + (size_t)w * (32 * CHUNK);
    float* yw = y + (size_t)w * (32 * CHUNK);

    float k[15];
#pragma unroll
    for (int i = 0; i < 15; i++) k[i] = g_coef[i];
    float z[6];
    const float* si = &g_states[(size_t)(w * 32 + lane) * 6];
#pragma unroll
    for (int j = 0; j < 6; j++) z[j] = si[j];

    int seg = lane >> 3;
    int off = (lane & 7) * 4;

    float4 pre[8];
#pragma unroll
    for (int q = 0; q < 8; q++)
        pre[q] = *(const float4*)(xw + (q * 4 + seg) * CHUNK + off);

#pragma unroll
    for (int t = 0; t < CHUNK / 32; t++) {
#pragma unroll
        for (int q = 0; q < 8; q++)
            *(float4*)&buf[q * 4 + seg][off] = pre[q];
        __syncwarp();
        if (t < CHUNK / 32 - 1) {
#pragma unroll
            for (int q = 0; q < 8; q++)
                pre[q] = *(const float4*)(xw + (q * 4 + seg) * CHUNK + (t + 1) * 32 + off);
        }
        float4* my = (float4*)buf[lane];
#pragma unroll
        for (int j = 0; j < 8; j++) {
            float4 v = my[j];
            float4 o;
            o.x = step_all(v.x, z, k);
            o.y = step_all(v.y, z, k);
            o.z = step_all(v.z, z, k);
            o.w = step_all(v.w, z, k);
            my[j] = o;
        }
        __syncwarp();
#pragma unroll
        for (int q = 0; q < 8; q++) {
            float4 v = *(const float4*)&buf[q * 4 + seg][off];
            *(float4*)(yw + (q * 4 + seg) * CHUNK + t * 32 + off) = v;
        }
        __syncwarp();
    }
}

// ------------------------------------------------------------ fused scan --

__device__ __forceinline__ void affine_step(float s[6], const float fv[6],
                                            const float T[36]) {
    float ns[6];
#pragma unroll
    for (int j = 0; j < 6; j++) {
        float acc = fv[j];
#pragma unroll
        for (int kk = 0; kk < 6; kk++) acc = fmaf(T[j * 6 + kk], s[kk], acc);
        ns[j] = acc;
    }
#pragma unroll
    for (int j = 0; j < 6; j++) s[j] = ns[j];
}

// One block per row; row's 22500 floats staged in padded dynamic smem
// (coalesced gmem IO; GPAD=181 odd -> conflict-free per-thread LDS rows).
__global__ __launch_bounds__(128) void scan_fused() {
    extern __shared__ float sf[];             // NGROUP * GPAD floats
    __shared__ float sT[36], sTg[36], sTsg[36];
    __shared__ float grp[NGROUP][6];
    __shared__ float sup[NSUP][6];
    int r = blockIdx.x, tid = threadIdx.x;
    float* gs = &g_states[(size_t)r * CROW * 6];

    for (int i = tid; i < CROW * 6; i += 128) {
        int g = i / (NGSZ * 6);
        sf[g * GPAD + (i - g * (NGSZ * 6))] = gs[i];
    }
    if (tid < 36) { sT[tid] = g_T[tid]; sTg[tid] = g_Tg[tid]; sTsg[tid] = g_Tsg[tid]; }
    __syncthreads();

    // phase 1: zero-entry scan within each group -> group final
    if (tid < NGROUP) {
        float T[36];
#pragma unroll
        for (int i = 0; i < 36; i++) T[i] = sT[i];
        const float* f = &sf[tid * GPAD];
        float s[6] = {0, 0, 0, 0, 0, 0};
        for (int i = 0; i < NGSZ; i++) {
            float fv[6];
#pragma unroll
            for (int j = 0; j < 6; j++) fv[j] = f[i * 6 + j];
            affine_step(s, fv, T);
        }
#pragma unroll
        for (int j = 0; j < 6; j++) grp[tid][j] = s[j];
    }
    __syncthreads();

    // phase 2a: zero-entry scan of 5 group finals -> supergroup final
    if (tid < NSUP) {
        float T[36];
#pragma unroll
        for (int i = 0; i < 36; i++) T[i] = sTg[i];
        float s[6] = {0, 0, 0, 0, 0, 0};
        for (int i = 0; i < NSUPG; i++) affine_step(s, grp[tid * NSUPG + i], T);
#pragma unroll
        for (int j = 0; j < 6; j++) sup[tid][j] = s[j];
    }
    __syncthreads();

    // phase 2b: serial scan over supergroups; sup[] becomes entry states
    if (tid == 0) {
        float T[36];
#pragma unroll
        for (int i = 0; i < 36; i++) T[i] = sTsg[i];
        float s[6] = {0, 0, 0, 0, 0, 0};
        for (int g = 0; g < NSUP; g++) {
            float fv[6];
#pragma unroll
            for (int j = 0; j < 6; j++) { fv[j] = sup[g][j]; sup[g][j] = s[j]; }
            affine_step(s, fv, T);
        }
    }
    __syncthreads();

    // phase 2c: group entry states from supergroup entry
    if (tid < NSUP) {
        float T[36];
#pragma unroll
        for (int i = 0; i < 36; i++) T[i] = sTg[i];
        float s[6];
#pragma unroll
        for (int j = 0; j < 6; j++) s[j] = sup[tid][j];
        for (int i = 0; i < NSUPG; i++) {
            float fv[6];
            int gi = tid * NSUPG + i;
#pragma unroll
            for (int j = 0; j < 6; j++) { fv[j] = grp[gi][j]; grp[gi][j] = s[j]; }
            affine_step(s, fv, T);
        }
    }
    __syncthreads();

    // phase 3: per-chunk entry states, overwrite staged finals
    if (tid < NGROUP) {
        float T[36];
#pragma unroll
        for (int i = 0; i < 36; i++) T[i] = sT[i];
        float* f = &sf[tid * GPAD];
        float s[6];
#pragma unroll
        for (int j = 0; j < 6; j++) s[j] = grp[tid][j];
        for (int i = 0; i < NGSZ; i++) {
            float fv[6];
#pragma unroll
            for (int j = 0; j < 6; j++) { fv[j] = f[i * 6 + j]; f[i * 6 + j] = s[j]; }
            affine_step(s, fv, T);
        }
    }
    __syncthreads();

    for (int i = tid; i < CROW * 6; i += 128) {
        int g = i / (NGSZ * 6);
        gs[i] = sf[g * GPAD + (i - g * (NGSZ * 6))];
    }
}

// ----------------------------------------------------------------- launch --

extern "C" void kernel_launch(void* const* d_in, const int* in_sizes, int n_in,
                              void* d_out, int out_size) {
    const float* x   = (const float*)d_in[0];
    const float* lg  = (const float*)d_in[1];
    const float* mg  = (const float*)d_in[2];
    const float* mfc = (const float*)d_in[3];
    const float* mq  = (const float*)d_in[4];
    const float* hg  = (const float*)d_in[5];
    float* y = (float*)d_out;

    cudaFuncSetAttribute(scan_fused, cudaFuncAttributeMaxDynamicSharedMemorySize,
                         SCAN_SMEM);

    setup_kernel<<<1, 256>>>(lg, mg, mfc, mq, hg);
    pass_zero<<<PBLK, 128>>>(x);
    scan_fused<<<NROW, 128, SCAN_SMEM>>>();
    pass_final<<<PBLK, 128>>>(x, y);
}

// round 7
// speedup vs baseline: 1.1244x; 1.0207x over previous
#include <cuda_runtime.h>
#include <math.h>

// ToneStack: 3 cascaded low-shelf biquads over x:[64, 480000] fp32.
// Blocked-recurrence decomposition:
//   pass_zero : per-chunk zero-state FINAL via weighted reduction
//               f = sum_n W[n]*x[n], W[n] = A^(127-n) b  (transposed table)
//   scan_fused: per-row 3-level affine scan s_{k+1} = T s_k + f_k (smem-staged)
//   pass_final: per-chunk serial filtering from exact entry state, writes y.

#define TLEN   480000
#define NROW   64
#define CHUNK  128
#define CROW   3750            // chunks per row
#define NCH    (NROW * CROW)   // 240000
#define NWARP  (NCH / 32)      // 7500
#define PBLK   (NWARP / 4)     // 1875 blocks of 4 warps
#define NGSZ   30              // chunks per group
#define NGROUP 125             // groups per row
#define NSUPG  5               // groups per supergroup
#define NSUP   25              // supergroups per row
#define GPAD   181             // NGSZ*6 + 1 (odd -> conflict-free smem rows)
#define SCAN_SMEM (NGROUP * GPAD * 4)

__device__ float g_coef[15];          // per stage: b0, c1, c2, -a1, -a2
__device__ float g_T[36];             // A^CHUNK
__device__ float g_Tg[36];            // T^NGSZ
__device__ float g_Tsg[36];           // Tg^NSUPG
__device__ float g_W6[6][CHUNK];      // transposed reduction weights
__device__ float g_states[NCH * 6];   // finals, then overwritten with entries

// ---------------------------------------------------------------- setup ----

__device__ void shelf_coefs(double fc, double gdb, double Q, double* out) {
    const double PI = 3.14159265358979323846;
    double A  = pow(10.0, gdb / 40.0);
    double w0 = 2.0 * PI * fc / 48000.0;
    double al = sin(w0) / (2.0 * Q);
    double cw = cos(w0);
    double sq = sqrt(A);
    double b0 = A * ((A + 1.0) - (A - 1.0) * cw + 2.0 * sq * al);
    double b1 = 2.0 * A * ((A - 1.0) - (A + 1.0) * cw);
    double b2 = A * ((A + 1.0) - (A - 1.0) * cw - 2.0 * sq * al);
    double a0 = (A + 1.0) + (A - 1.0) * cw + 2.0 * sq * al;
    double a1 = -2.0 * ((A - 1.0) + (A + 1.0) * cw);
    double a2 = (A + 1.0) + (A - 1.0) * cw - 2.0 * sq * al;
    b0 /= a0; b1 /= a0; b2 /= a0; a1 /= a0; a2 /= a0;
    out[0] = b0;
    out[1] = b1 - a1 * b0;   // c1
    out[2] = b2 - a2 * b0;   // c2
    out[3] = -a1;
    out[4] = -a2;
}

#define MATMUL(D, A_, B_)                                                     \
    do {                                                                      \
        if (tid < 36) {                                                       \
            int r_ = tid / 6, c_ = tid % 6;                                   \
            float acc_ = 0.f;                                                 \
            for (int k_ = 0; k_ < 6; k_++)                                    \
                acc_ += (A_)[r_ * 6 + k_] * (B_)[k_ * 6 + c_];                \
            (D)[tid] = acc_;                                                  \
        }                                                                     \
        __syncthreads();                                                      \
    } while (0)

__global__ void setup_kernel(const float* lg, const float* mg, const float* mfc,
                             const float* mq, const float* hg) {
    __shared__ double scoef[15];
    __shared__ double db[6];
    __shared__ float sP[7][36];        // A^(2^k), k = 0..6
    __shared__ float M0[36], M1[36], M2[36], M3[36], M4[36];
    int tid = threadIdx.x;

    if (tid == 0) {
        double c[5];
        shelf_coefs(120.0, (double)*lg, (double)0.707f, c);
        for (int i = 0; i < 5; i++) { scoef[i] = c[i];      g_coef[i]      = (float)c[i]; }
        shelf_coefs((double)*mfc, (double)*mg, (double)*mq, c);
        for (int i = 0; i < 5; i++) { scoef[5 + i] = c[i];  g_coef[5 + i]  = (float)c[i]; }
        shelf_coefs(4000.0, (double)*hg, (double)0.707f, c);
        for (int i = 0; i < 5; i++) { scoef[10 + i] = c[i]; g_coef[10 + i] = (float)c[i]; }
    }
    __syncthreads();

    // One-step 6x6 homogeneous matrix A: column j = step(e_j, x=0)
    if (tid < 6) {
        double z[6] = {0, 0, 0, 0, 0, 0};
        z[tid] = 1.0;
        double u = 0.0;
        double ns[6];
        for (int st = 0; st < 3; st++) {
            double b0  = scoef[st * 5 + 0], c1 = scoef[st * 5 + 1], c2 = scoef[st * 5 + 2];
            double na1 = scoef[st * 5 + 3], na2 = scoef[st * 5 + 4];
            double z1 = z[2 * st], z2 = z[2 * st + 1];
            double y = b0 * u + z1;
            ns[2 * st]     = c1 * u + na1 * z1 + z2;
            ns[2 * st + 1] = c2 * u + na2 * z1;
            u = y;
        }
        for (int i = 0; i < 6; i++) M0[i * 6 + tid] = (float)ns[i];
    }
    // Input vector b: state update from z=0, u=1
    if (tid == 0) {
        double y0 = scoef[0];                 // b0_1
        double y1 = scoef[5] * y0;            // b0_2 * y0
        db[0] = scoef[1];  db[1] = scoef[2];
        db[2] = scoef[6] * y0;   db[3] = scoef[7] * y0;
        db[4] = scoef[11] * y1;  db[5] = scoef[12] * y1;
    }
    __syncthreads();

    // Squaring chain; stash A^(2^k) along the way.
    if (tid < 36) sP[0][tid] = M0[tid];
    __syncthreads();
    MATMUL(M1, M0, M0);   if (tid < 36) sP[1][tid] = M1[tid];   // A^2
    MATMUL(M0, M1, M1);   if (tid < 36) sP[2][tid] = M0[tid];   // A^4
    MATMUL(M1, M0, M0);   if (tid < 36) sP[3][tid] = M1[tid];   // A^8
    MATMUL(M0, M1, M1);   if (tid < 36) sP[4][tid] = M0[tid];   // A^16
    MATMUL(M1, M0, M0);   if (tid < 36) sP[5][tid] = M1[tid];   // A^32
    MATMUL(M0, M1, M1);   if (tid < 36) sP[6][tid] = M0[tid];   // A^64
    MATMUL(M1, M0, M0);                                          // A^128 = T
    if (tid < 36) { g_T[tid] = M1[tid]; M0[tid] = M1[tid]; }
    __syncthreads();

    // Tg = T^30 ; Tsg = Tg^5
    MATMUL(M1, M0, M0);   // T^2
    MATMUL(M2, M1, M1);   // T^4
    MATMUL(M3, M2, M2);   // T^8
    MATMUL(M4, M3, M3);   // T^16
    MATMUL(M0, M4, M3);   // T^24
    MATMUL(M3, M0, M2);   // T^28
    MATMUL(M2, M3, M1);   // T^30 = Tg
    if (tid < 36) g_Tg[tid] = M2[tid];
    __syncthreads();
    MATMUL(M1, M2, M2);   // Tg^2
    MATMUL(M0, M1, M1);   // Tg^4
    MATMUL(M4, M0, M2);   // Tg^5 = Tsg
    if (tid < 36) g_Tsg[tid] = M4[tid];
    __syncthreads();

    // W[n] = A^(127-n) b, one thread per n via binary power application
    // (powers of A commute, so application order is free).
    if (tid < CHUNK) {
        int e = CHUNK - 1 - tid;
        float v[6];
#pragma unroll
        for (int j = 0; j < 6; j++) v[j] = (float)db[j];
#pragma unroll
        for (int k = 0; k < 7; k++) {
            if ((e >> k) & 1) {
                float nv[6];
#pragma unroll
                for (int j = 0; j < 6; j++) {
                    float acc = 0.f;
#pragma unroll
                    for (int kk = 0; kk < 6; kk++)
                        acc = fmaf(sP[k][j * 6 + kk], v[kk], acc);
                    nv[j] = acc;
                }
#pragma unroll
                for (int j = 0; j < 6; j++) v[j] = nv[j];
            }
        }
#pragma unroll
        for (int j = 0; j < 6; j++) g_W6[j][tid] = v[j];
    }
}

// -------------------------------------------------------------- filtering --

__device__ __forceinline__ float step_all(float u, float z[6], const float k[15]) {
    float y0 = fmaf(k[0], u, z[0]);
    float t0 = fmaf(k[3], z[0], z[1]);
    z[1] = fmaf(k[2], u, k[4] * z[0]);
    z[0] = fmaf(k[1], u, t0);
    float y1 = fmaf(k[5], y0, z[2]);
    float t1 = fmaf(k[8], z[2], z[3]);
    z[3] = fmaf(k[7], y0, k[9] * z[2]);
    z[2] = fmaf(k[6], y0, t1);
    float y2 = fmaf(k[10], y1, z[4]);
    float t2 = fmaf(k[13], z[4], z[5]);
    z[5] = fmaf(k[12], y1, k[14] * z[4]);
    z[4] = fmaf(k[11], y1, t2);
    return y2;
}

// Tile: 32 chunks x 32 samples, rows padded to 36 floats. seg = lane>>3,
// off = (lane&7)*4: every LDG/STG.128 covers 4 full 128B lines.

// pass_zero: weighted reduction with float4 weight loads (W transposed).
__global__ __launch_bounds__(128) void pass_zero(const float* __restrict__ x) {
    __shared__ float sbuf[4][32][36];
    __shared__ float sw6[6][CHUNK];
    int wslot = threadIdx.x >> 5;
    int w = blockIdx.x * 4 + wslot;
    int lane = threadIdx.x & 31;
    float (*buf)[36] = sbuf[wslot];
    const float* xw = x + (size_t)w * (32 * CHUNK);

    for (int i = threadIdx.x; i < 6 * CHUNK / 4; i += 128)
        ((float4*)sw6)[i] = ((const float4*)g_W6)[i];
    __syncthreads();

    float f0 = 0.f, f1 = 0.f, f2 = 0.f, f3 = 0.f, f4 = 0.f, f5 = 0.f;
    int seg = lane >> 3;
    int off = (lane & 7) * 4;

    float4 pre[8];
#pragma unroll
    for (int q = 0; q < 8; q++)
        pre[q] = *(const float4*)(xw + (q * 4 + seg) * CHUNK + off);

#pragma unroll
    for (int t = 0; t < CHUNK / 32; t++) {
#pragma unroll
        for (int q = 0; q < 8; q++)
            *(float4*)&buf[q * 4 + seg][off] = pre[q];
        __syncwarp();
        if (t < CHUNK / 32 - 1) {
#pragma unroll
            for (int q = 0; q < 8; q++)
                pre[q] = *(const float4*)(xw + (q * 4 + seg) * CHUNK + (t + 1) * 32 + off);
        }
        const float4* my = (const float4*)buf[lane];
#pragma unroll
        for (int j = 0; j < 8; j++) {
            float4 v = my[j];
            int n = t * 32 + j * 4;
            float4 w0 = *(const float4*)&sw6[0][n];
            float4 w1 = *(const float4*)&sw6[1][n];
            float4 w2 = *(const float4*)&sw6[2][n];
            float4 w3 = *(const float4*)&sw6[3][n];
            float4 w4 = *(const float4*)&sw6[4][n];
            float4 w5 = *(const float4*)&sw6[5][n];
            f0 = fmaf(v.w, w0.w, fmaf(v.z, w0.z, fmaf(v.y, w0.y, fmaf(v.x, w0.x, f0))));
            f1 = fmaf(v.w, w1.w, fmaf(v.z, w1.z, fmaf(v.y, w1.y, fmaf(v.x, w1.x, f1))));
            f2 = fmaf(v.w, w2.w, fmaf(v.z, w2.z, fmaf(v.y, w2.y, fmaf(v.x, w2.x, f2))));
            f3 = fmaf(v.w, w3.w, fmaf(v.z, w3.z, fmaf(v.y, w3.y, fmaf(v.x, w3.x, f3))));
            f4 = fmaf(v.w, w4.w, fmaf(v.z, w4.z, fmaf(v.y, w4.y, fmaf(v.x, w4.x, f4))));
            f5 = fmaf(v.w, w5.w, fmaf(v.z, w5.z, fmaf(v.y, w5.y, fmaf(v.x, w5.x, f5))));
        }
        __syncwarp();
    }
    float* f = &g_states[(size_t)(w * 32 + lane) * 6];
    f[0] = f0; f[1] = f1; f[2] = f2; f[3] = f3; f[4] = f4; f[5] = f5;
}

__global__ __launch_bounds__(128) void pass_final(const float* __restrict__ x,
                                                  float* __restrict__ y) {
    __shared__ float sbuf[4][32][36];
    int wslot = threadIdx.x >> 5;
    int w = blockIdx.x * 4 + wslot;
    int lane = threadIdx.x & 31;
    float (*buf)[36] = sbuf[wslot];
    const float* xw = x + (size_t)w * (32 * CHUNK);
    float* yw = y + (size_t)w * (32 * CHUNK);

    float k[15];
#pragma unroll
    for (int i = 0; i < 15; i++) k[i] = g_coef[i];
    float z[6];
    const float* si = &g_states[(size_t)(w * 32 + lane) * 6];
#pragma unroll
    for (int j = 0; j < 6; j++) z[j] = si[j];

    int seg = lane >> 3;
    int off = (lane & 7) * 4;

    float4 pre[8];
#pragma unroll
    for (int q = 0; q < 8; q++)
        pre[q] = *(const float4*)(xw + (q * 4 + seg) * CHUNK + off);

#pragma unroll
    for (int t = 0; t < CHUNK / 32; t++) {
#pragma unroll
        for (int q = 0; q < 8; q++)
            *(float4*)&buf[q * 4 + seg][off] = pre[q];
        __syncwarp();
        if (t < CHUNK / 32 - 1) {
#pragma unroll
            for (int q = 0; q < 8; q++)
                pre[q] = *(const float4*)(xw + (q * 4 + seg) * CHUNK + (t + 1) * 32 + off);
        }
        float4* my = (float4*)buf[lane];
#pragma unroll
        for (int j = 0; j < 8; j++) {
            float4 v = my[j];
            float4 o;
            o.x = step_all(v.x, z, k);
            o.y = step_all(v.y, z, k);
            o.z = step_all(v.z, z, k);
            o.w = step_all(v.w, z, k);
            my[j] = o;
        }
        __syncwarp();
#pragma unroll
        for (int q = 0; q < 8; q++) {
            float4 v = *(const float4*)&buf[q * 4 + seg][off];
            *(float4*)(yw + (q * 4 + seg) * CHUNK + t * 32 + off) = v;
        }
        __syncwarp();
    }
}

// ------------------------------------------------------------ fused scan --

__device__ __forceinline__ void affine_step(float s[6], const float fv[6],
                                            const float T[36]) {
    float ns[6];
#pragma unroll
    for (int j = 0; j < 6; j++) {
        float acc = fv[j];
#pragma unroll
        for (int kk = 0; kk < 6; kk++) acc = fmaf(T[j * 6 + kk], s[kk], acc);
        ns[j] = acc;
    }
#pragma unroll
    for (int j = 0; j < 6; j++) s[j] = ns[j];
}

// One block per row; row's 22500 floats staged in padded dynamic smem.
__global__ __launch_bounds__(128) void scan_fused() {
    extern __shared__ float sf[];             // NGROUP * GPAD floats
    __shared__ float sT[36], sTg[36], sTsg[36];
    __shared__ float grp[NGROUP][6];
    __shared__ float sup[NSUP][6];
    int r = blockIdx.x, tid = threadIdx.x;
    float* gs = &g_states[(size_t)r * CROW * 6];

    for (int i = tid; i < CROW * 6; i += 128) {
        int g = i / (NGSZ * 6);
        sf[g * GPAD + (i - g * (NGSZ * 6))] = gs[i];
    }
    if (tid < 36) { sT[tid] = g_T[tid]; sTg[tid] = g_Tg[tid]; sTsg[tid] = g_Tsg[tid]; }
    __syncthreads();

    // phase 1: zero-entry scan within each group -> group final
    if (tid < NGROUP) {
        float T[36];
#pragma unroll
        for (int i = 0; i < 36; i++) T[i] = sT[i];
        const float* f = &sf[tid * GPAD];
        float s[6] = {0, 0, 0, 0, 0, 0};
        for (int i = 0; i < NGSZ; i++) {
            float fv[6];
#pragma unroll
            for (int j = 0; j < 6; j++) fv[j] = f[i * 6 + j];
            affine_step(s, fv, T);
        }
#pragma unroll
        for (int j = 0; j < 6; j++) grp[tid][j] = s[j];
    }
    __syncthreads();

    // phase 2a: zero-entry scan of 5 group finals -> supergroup final
    if (tid < NSUP) {
        float T[36];
#pragma unroll
        for (int i = 0; i < 36; i++) T[i] = sTg[i];
        float s[6] = {0, 0, 0, 0, 0, 0};
        for (int i = 0; i < NSUPG; i++) affine_step(s, grp[tid * NSUPG + i], T);
#pragma unroll
        for (int j = 0; j < 6; j++) sup[tid][j] = s[j];
    }
    __syncthreads();

    // phase 2b: serial scan over supergroups; sup[] becomes entry states
    if (tid == 0) {
        float T[36];
#pragma unroll
        for (int i = 0; i < 36; i++) T[i] = sTsg[i];
        float s[6] = {0, 0, 0, 0, 0, 0};
        for (int g = 0; g < NSUP; g++) {
            float fv[6];
#pragma unroll
            for (int j = 0; j < 6; j++) { fv[j] = sup[g][j]; sup[g][j] = s[j]; }
            affine_step(s, fv, T);
        }
    }
    __syncthreads();

    // phase 2c: group entry states from supergroup entry
    if (tid < NSUP) {
        float T[36];
#pragma unroll
        for (int i = 0; i < 36; i++) T[i] = sTg[i];
        float s[6];
#pragma unroll
        for (int j = 0; j < 6; j++) s[j] = sup[tid][j];
        for (int i = 0; i < NSUPG; i++) {
            float fv[6];
            int gi = tid * NSUPG + i;
#pragma unroll
            for (int j = 0; j < 6; j++) { fv[j] = grp[gi][j]; grp[gi][j] = s[j]; }
            affine_step(s, fv, T);
        }
    }
    __syncthreads();

    // phase 3: per-chunk entry states, overwrite staged finals
    if (tid < NGROUP) {
        float T[36];
#pragma unroll
        for (int i = 0; i < 36; i++) T[i] = sT[i];
        float* f = &sf[tid * GPAD];
        float s[6];
#pragma unroll
        for (int j = 0; j < 6; j++) s[j] = grp[tid][j];
        for (int i = 0; i < NGSZ; i++) {
            float fv[6];
#pragma unroll
            for (int j = 0; j < 6; j++) { fv[j] = f[i * 6 + j]; f[i * 6 + j] = s[j]; }
            affine_step(s, fv, T);
        }
    }
    __syncthreads();

    for (int i = tid; i < CROW * 6; i += 128) {
        int g = i / (NGSZ * 6);
        gs[i] = sf[g * GPAD + (i - g * (NGSZ * 6))];
    }
}

// ----------------------------------------------------------------- launch --

extern "C" void kernel_launch(void* const* d_in, const int* in_sizes, int n_in,
                              void* d_out, int out_size) {
    const float* x   = (const float*)d_in[0];
    const float* lg  = (const float*)d_in[1];
    const float* mg  = (const float*)d_in[2];
    const float* mfc = (const float*)d_in[3];
    const float* mq  = (const float*)d_in[4];
    const float* hg  = (const float*)d_in[5];
    float* y = (float*)d_out;

    cudaFuncSetAttribute(scan_fused, cudaFuncAttributeMaxDynamicSharedMemorySize,
                         SCAN_SMEM);

    setup_kernel<<<1, 256>>>(lg, mg, mfc, mq, hg);
    pass_zero<<<PBLK, 128>>>(x);
    scan_fused<<<NROW, 128, SCAN_SMEM>>>();
    pass_final<<<PBLK, 128>>>(x, y);
}